// round 10
// baseline (speedup 1.0000x reference)
#include <cuda_runtime.h>
#include <cstdint>

// out = x * (1 - mask), mask broadcasts over C=3.
// x:    [B=64, C=3, H=512, W=512] f32
// mask: [B=64, 1,   H=512, W=512] f32, exactly 0/1 in large rectangles.
//
// R5 trick: where mask==1 output is exactly 0.0f -> skip x loads.
// R9: VPT=4 thread-interleaved positions (v, v+256, v+512, v+768) --
// every access warp-coalesced, MLP up to 16, grid 4096 (~3.5 waves).

static constexpr int Cc = 3;
static constexpr int HW = 512 * 512;
static constexpr int HW4 = HW / 4;        // 65536 float4 per plane
static constexpr int THREADS = 256;
static constexpr int VPT = 4;             // interleaved positions per thread

__device__ __forceinline__ float4 blend(float4 xv, float4 m) {
    return make_float4(xv.x * (1.0f - m.x), xv.y * (1.0f - m.y),
                       xv.z * (1.0f - m.z), xv.w * (1.0f - m.w));
}

__device__ __forceinline__ bool allone(float4 m) {
    return (m.x == 1.0f) & (m.y == 1.0f) & (m.z == 1.0f) & (m.w == 1.0f);
}

__global__ __launch_bounds__(THREADS, 8)
void random_mask_kernel(const float4* __restrict__ x,
                        const float4* __restrict__ mask,
                        float4* __restrict__ out) {
    const int b  = blockIdx.y;                                      // batch
    const int v0 = blockIdx.x * (THREADS * VPT) + threadIdx.x;

    const long long mbase = (long long)b * HW4;
    const long long xbase = (long long)(b * Cc) * HW4;

    // All mask loads up front.
    float4 m[VPT];
#pragma unroll
    for (int i = 0; i < VPT; i++) m[i] = mask[mbase + v0 + i * THREADS];

    bool live[VPT];
    bool any_live = false;
#pragma unroll
    for (int i = 0; i < VPT; i++) { live[i] = !allone(m[i]); any_live |= live[i]; }

    const float4 z = make_float4(0.0f, 0.0f, 0.0f, 0.0f);

    if (!any_live) {
        // All 4 positions fully masked: 12 zero stores, no x traffic.
#pragma unroll
        for (int i = 0; i < VPT; i++) {
            const long long p = xbase + v0 + i * THREADS;
            out[p] = z; out[p + HW4] = z; out[p + 2 * HW4] = z;
        }
        return;
    }

    // Issue every live x load up front (predicated; dead lanes fetch nothing).
    float4 a[VPT], bb[VPT], c[VPT];
#pragma unroll
    for (int i = 0; i < VPT; i++) {
        const long long p = xbase + v0 + i * THREADS;
        if (live[i]) a[i]  = x[p];
    }
#pragma unroll
    for (int i = 0; i < VPT; i++) {
        const long long p = xbase + v0 + i * THREADS;
        if (live[i]) bb[i] = x[p + HW4];
    }
#pragma unroll
    for (int i = 0; i < VPT; i++) {
        const long long p = xbase + v0 + i * THREADS;
        if (live[i]) c[i]  = x[p + 2 * HW4];
    }

#pragma unroll
    for (int i = 0; i < VPT; i++) {
        const long long p = xbase + v0 + i * THREADS;
        if (live[i]) {
            out[p]           = blend(a[i],  m[i]);
            out[p + HW4]     = blend(bb[i], m[i]);
            out[p + 2 * HW4] = blend(c[i],  m[i]);
        } else {
            out[p] = z; out[p + HW4] = z; out[p + 2 * HW4] = z;
        }
    }
}

extern "C" void kernel_launch(void* const* d_in, const int* in_sizes, int n_in,
                              void* d_out, int out_size) {
    const float4* x    = (const float4*)d_in[0];
    const float4* mask = (const float4*)d_in[1];
    float4* out        = (float4*)d_out;

    const int B = in_sizes[1] / HW;                   // 64
    dim3 grid(HW4 / (THREADS * VPT), B);              // (64, 64)
    random_mask_kernel<<<grid, THREADS>>>(x, mask, out);
}

// round 11
// speedup vs baseline: 2.0494x; 2.0494x over previous
#include <cuda_runtime.h>
#include <cstdint>

// out = x * (1 - mask), mask broadcasts over C=3.
// x:    [B=64, C=3, H=512, W=512] f32
// mask: [B=64, 1,   H=512, W=512] f32, exactly 0/1 in large rectangles.
//
// R5 trick: where mask==1 output is exactly 0.0f -> skip the x loads.
// R8 body: VPT=2 thread-interleaved (v, v+256), all accesses warp-coalesced,
// fits the 32-reg budget (no spills).
// R10: grid TRANSPOSED to (batch, posblock) so consecutively-scheduled CTAs
// span 64 different images (different mask modes) -> each scheduling wave
// gets a uniform mix of light (masked) and heavy (live) CTAs, removing the
// per-wave load imbalance that left ~24% of DRAM cycles idle.

static constexpr int Cc = 3;
static constexpr int HW = 512 * 512;
static constexpr int HW4 = HW / 4;        // 65536 float4 per plane
static constexpr int THREADS = 256;
static constexpr int VPT = 2;             // interleaved positions per thread

__device__ __forceinline__ float4 blend(float4 xv, float4 m) {
    return make_float4(xv.x * (1.0f - m.x), xv.y * (1.0f - m.y),
                       xv.z * (1.0f - m.z), xv.w * (1.0f - m.w));
}

__device__ __forceinline__ bool allone(float4 m) {
    return (m.x == 1.0f) & (m.y == 1.0f) & (m.z == 1.0f) & (m.w == 1.0f);
}

__global__ __launch_bounds__(THREADS, 8)
void random_mask_kernel(const float4* __restrict__ x,
                        const float4* __restrict__ mask,
                        float4* __restrict__ out) {
    const int b  = blockIdx.x;                                      // batch (fast axis)
    const int v0 = blockIdx.y * (THREADS * VPT) + threadIdx.x;      // pos 0
    const int v1 = v0 + THREADS;                                    // pos 1

    const long long mbase = (long long)b * HW4;
    const long long xbase = (long long)(b * Cc) * HW4;

    const float4 m0 = mask[mbase + v0];
    const float4 m1 = mask[mbase + v1];

    const bool fm0 = allone(m0);
    const bool fm1 = allone(m1);

    const long long p0 = xbase + v0;
    const long long p1 = xbase + v1;
    const float4 z = make_float4(0.0f, 0.0f, 0.0f, 0.0f);

    if (fm0 & fm1) {
        out[p0] = z; out[p0 + HW4] = z; out[p0 + 2 * HW4] = z;
        out[p1] = z; out[p1 + HW4] = z; out[p1 + 2 * HW4] = z;
        return;
    }

    if (!fm0 & !fm1) {
        // Both live: issue all 6 loads up front (MLP 8 incl. masks).
        const float4 a0 = x[p0];
        const float4 a1 = x[p1];
        const float4 b0 = x[p0 + HW4];
        const float4 b1 = x[p1 + HW4];
        const float4 c0 = x[p0 + 2 * HW4];
        const float4 c1 = x[p1 + 2 * HW4];
        out[p0]           = blend(a0, m0);
        out[p1]           = blend(a1, m1);
        out[p0 + HW4]     = blend(b0, m0);
        out[p1 + HW4]     = blend(b1, m1);
        out[p0 + 2 * HW4] = blend(c0, m0);
        out[p1 + 2 * HW4] = blend(c1, m1);
        return;
    }

    // Mixed: exactly one position is fully masked.
    const long long pl = fm0 ? p1 : p0;      // live position
    const long long pm = fm0 ? p0 : p1;      // masked position
    const float4    ml = fm0 ? m1 : m0;

    const float4 a  = x[pl];
    const float4 bb = x[pl + HW4];
    const float4 c  = x[pl + 2 * HW4];

    out[pm] = z; out[pm + HW4] = z; out[pm + 2 * HW4] = z;
    out[pl]           = blend(a,  ml);
    out[pl + HW4]     = blend(bb, ml);
    out[pl + 2 * HW4] = blend(c,  ml);
}

extern "C" void kernel_launch(void* const* d_in, const int* in_sizes, int n_in,
                              void* d_out, int out_size) {
    const float4* x    = (const float4*)d_in[0];
    const float4* mask = (const float4*)d_in[1];
    float4* out        = (float4*)d_out;

    const int B = in_sizes[1] / HW;                   // 64
    dim3 grid(B, HW4 / (THREADS * VPT));              // (64, 128) transposed
    random_mask_kernel<<<grid, THREADS>>>(x, mask, out);
}

// round 12
// speedup vs baseline: 2.1013x; 1.0253x over previous
#include <cuda_runtime.h>
#include <cstdint>

// out = x * (1 - mask), mask broadcasts over C=3.
// x:    [B=64, C=3, H=512, W=512] f32
// mask: [B=64, 1,   H=512, W=512] f32, exactly 0/1 in large rectangles.
//
// R5 trick: where mask==1 output is exactly 0.0f -> skip the x loads.
// R11: 256-bit global accesses (sm_100+ ld/st.global.v8.f32). Each thread
// owns TWO ADJACENT float4 positions as one 32B access: warp covers 1024B
// contiguous (no fragmentation, unlike R6's twin-LDG.128 layout), and the
// L1/LSU request count halves vs R8. No __launch_bounds__ min-blocks so the
// ~48-reg body doesn't spill (R9's failure mode).

static constexpr int Cc = 3;
static constexpr int HW = 512 * 512;
static constexpr int HW4 = HW / 4;        // 65536 float4 per plane
static constexpr int THREADS = 256;

__device__ __forceinline__ void ldg256(const float4* p, float4& a, float4& b) {
    asm volatile("ld.global.v8.f32 {%0,%1,%2,%3,%4,%5,%6,%7}, [%8];"
                 : "=f"(a.x), "=f"(a.y), "=f"(a.z), "=f"(a.w),
                   "=f"(b.x), "=f"(b.y), "=f"(b.z), "=f"(b.w)
                 : "l"(p));
}

__device__ __forceinline__ void stg256(float4* p, float4 a, float4 b) {
    asm volatile("st.global.v8.f32 [%0], {%1,%2,%3,%4,%5,%6,%7,%8};"
                 :: "l"(p),
                    "f"(a.x), "f"(a.y), "f"(a.z), "f"(a.w),
                    "f"(b.x), "f"(b.y), "f"(b.z), "f"(b.w)
                 : "memory");
}

__device__ __forceinline__ float4 blend(float4 xv, float4 m) {
    return make_float4(xv.x * (1.0f - m.x), xv.y * (1.0f - m.y),
                       xv.z * (1.0f - m.z), xv.w * (1.0f - m.w));
}

__device__ __forceinline__ bool allone(float4 m) {
    return (m.x == 1.0f) & (m.y == 1.0f) & (m.z == 1.0f) & (m.w == 1.0f);
}

__global__ __launch_bounds__(THREADS)
void random_mask_kernel(const float4* __restrict__ x,
                        const float4* __restrict__ mask,
                        float4* __restrict__ out) {
    const int b = blockIdx.y;                                     // batch
    // Two adjacent float4 positions per thread, one v8 access each.
    const int v = (blockIdx.x * THREADS + threadIdx.x) * 2;       // 32B aligned

    const long long mi = (long long)b * HW4 + v;
    const long long x0 = (long long)(b * Cc) * HW4 + v;

    float4 m0, m1;
    ldg256(&mask[mi], m0, m1);

    const bool masked = allone(m0) & allone(m1);

    const float4 z = make_float4(0.0f, 0.0f, 0.0f, 0.0f);

    if (masked) {
        stg256(&out[x0],           z, z);
        stg256(&out[x0 + HW4],     z, z);
        stg256(&out[x0 + 2 * HW4], z, z);
        return;
    }

    float4 a0, a1, b0, b1, c0, c1;
    ldg256(&x[x0],           a0, a1);
    ldg256(&x[x0 + HW4],     b0, b1);
    ldg256(&x[x0 + 2 * HW4], c0, c1);

    stg256(&out[x0],           blend(a0, m0), blend(a1, m1));
    stg256(&out[x0 + HW4],     blend(b0, m0), blend(b1, m1));
    stg256(&out[x0 + 2 * HW4], blend(c0, m0), blend(c1, m1));
}

extern "C" void kernel_launch(void* const* d_in, const int* in_sizes, int n_in,
                              void* d_out, int out_size) {
    const float4* x    = (const float4*)d_in[0];
    const float4* mask = (const float4*)d_in[1];
    float4* out        = (float4*)d_out;

    const int B = in_sizes[1] / HW;                   // 64
    dim3 grid(HW4 / (THREADS * 2), B);                // (128, 64)
    random_mask_kernel<<<grid, THREADS>>>(x, mask, out);
}

// round 14
// speedup vs baseline: 2.1169x; 1.0074x over previous
#include <cuda_runtime.h>
#include <cstdint>

// out = x * (1 - mask), mask broadcasts over C=3.
// x:    [B=64, C=3, H=512, W=512] f32
// mask: [B=64, 1,   H=512, W=512] f32, exactly 0/1 in large rectangles.
//
// R5 trick: where mask==1 output is exactly 0.0f -> skip the x loads.
// R11: 256-bit global accesses (ld/st.global.v8.f32), one 32B chunk per
// thread, warp = 1024B contiguous.
// R12: 128-thread CTAs (16384 blocks) -- finer scheduling granularity so
// short masked CTAs backfill tightly around long live CTAs, closing the
// achieved-occupancy gap (58% -> target ~70%).

static constexpr int Cc = 3;
static constexpr int HW = 512 * 512;
static constexpr int HW4 = HW / 4;        // 65536 float4 per plane
static constexpr int THREADS = 128;

__device__ __forceinline__ void ldg256(const float4* p, float4& a, float4& b) {
    asm volatile("ld.global.v8.f32 {%0,%1,%2,%3,%4,%5,%6,%7}, [%8];"
                 : "=f"(a.x), "=f"(a.y), "=f"(a.z), "=f"(a.w),
                   "=f"(b.x), "=f"(b.y), "=f"(b.z), "=f"(b.w)
                 : "l"(p));
}

__device__ __forceinline__ void stg256(float4* p, float4 a, float4 b) {
    asm volatile("st.global.v8.f32 [%0], {%1,%2,%3,%4,%5,%6,%7,%8};"
                 :: "l"(p),
                    "f"(a.x), "f"(a.y), "f"(a.z), "f"(a.w),
                    "f"(b.x), "f"(b.y), "f"(b.z), "f"(b.w)
                 : "memory");
}

__device__ __forceinline__ float4 blend(float4 xv, float4 m) {
    return make_float4(xv.x * (1.0f - m.x), xv.y * (1.0f - m.y),
                       xv.z * (1.0f - m.z), xv.w * (1.0f - m.w));
}

__device__ __forceinline__ bool allone(float4 m) {
    return (m.x == 1.0f) & (m.y == 1.0f) & (m.z == 1.0f) & (m.w == 1.0f);
}

__global__ __launch_bounds__(THREADS)
void random_mask_kernel(const float4* __restrict__ x,
                        const float4* __restrict__ mask,
                        float4* __restrict__ out) {
    const int b = blockIdx.y;                                     // batch
    // Two adjacent float4 positions per thread, one v8 access each.
    const int v = (blockIdx.x * THREADS + threadIdx.x) * 2;       // 32B aligned

    const long long mi = (long long)b * HW4 + v;
    const long long x0 = (long long)(b * Cc) * HW4 + v;

    float4 m0, m1;
    ldg256(&mask[mi], m0, m1);

    const bool masked = allone(m0) & allone(m1);

    const float4 z = make_float4(0.0f, 0.0f, 0.0f, 0.0f);

    if (masked) {
        stg256(&out[x0],           z, z);
        stg256(&out[x0 + HW4],     z, z);
        stg256(&out[x0 + 2 * HW4], z, z);
        return;
    }

    float4 a0, a1, b0, b1, c0, c1;
    ldg256(&x[x0],           a0, a1);
    ldg256(&x[x0 + HW4],     b0, b1);
    ldg256(&x[x0 + 2 * HW4], c0, c1);

    stg256(&out[x0],           blend(a0, m0), blend(a1, m1));
    stg256(&out[x0 + HW4],     blend(b0, m0), blend(b1, m1));
    stg256(&out[x0 + 2 * HW4], blend(c0, m0), blend(c1, m1));
}

extern "C" void kernel_launch(void* const* d_in, const int* in_sizes, int n_in,
                              void* d_out, int out_size) {
    const float4* x    = (const float4*)d_in[0];
    const float4* mask = (const float4*)d_in[1];
    float4* out        = (float4*)d_out;

    const int B = in_sizes[1] / HW;                   // 64
    dim3 grid(HW4 / (THREADS * 2), B);                // (256, 64)
    random_mask_kernel<<<grid, THREADS>>>(x, mask, out);
}